// round 1
// baseline (speedup 1.0000x reference)
#include <cuda_runtime.h>
#include <math.h>

// Problem constants (fixed by setup_inputs)
#define D_DIM   512
#define D_VEC4  (D_DIM / 4)   // 128 float4 per row
#define P_DIM   8
#define Q_DIM   32
#define MARGIN  1.0f
#define L2W     0.005f
#define EPSF    1e-6f
#define MAXN    4096

// Scratch (no allocations allowed)
__device__ float g_per_anchor[MAXN];
__device__ float g_norm[MAXN];

__device__ __forceinline__ float warpSum(float v) {
#pragma unroll
    for (int o = 16; o > 0; o >>= 1) v += __shfl_xor_sync(0xffffffffu, v, o);
    return v;
}
__device__ __forceinline__ float warpMax(float v) {
#pragma unroll
    for (int o = 16; o > 0; o >>= 1) v = fmaxf(v, __shfl_xor_sync(0xffffffffu, v, o));
    return v;
}

__device__ __forceinline__ float sqdiff4(float4 a, float4 b) {
    float dx = a.x - b.x + EPSF;
    float dy = a.y - b.y + EPSF;
    float dz = a.z - b.z + EPSF;
    float dw = a.w - b.w + EPSF;
    return dx * dx + dy * dy + dz * dz + dw * dw;
}

__global__ void __launch_bounds__(128)
anchor_kernel(const float* __restrict__ batch,
              const int* __restrict__ anchors,
              const int* __restrict__ pos_idx,
              const int* __restrict__ neg_idx,
              int N) {
    int gw = blockIdx.x * 4 + (threadIdx.x >> 5);   // global warp = anchor index
    int lane = threadIdx.x & 31;
    if (gw >= N) return;

    const float4* bb = (const float4*)batch;

    // Row `gw` for the L2-regularizer norm term
    size_t rw = (size_t)gw * D_VEC4;
    float4 w0 = bb[rw + lane];
    float4 w1 = bb[rw + lane + 32];
    float4 w2 = bb[rw + lane + 64];
    float4 w3 = bb[rw + lane + 96];
    float nrm = w0.x * w0.x + w0.y * w0.y + w0.z * w0.z + w0.w * w0.w
              + w1.x * w1.x + w1.y * w1.y + w1.z * w1.z + w1.w * w1.w
              + w2.x * w2.x + w2.y * w2.y + w2.z * w2.z + w2.w * w2.w
              + w3.x * w3.x + w3.y * w3.y + w3.z * w3.z + w3.w * w3.w;
    nrm = warpSum(nrm);
    if (lane == 0) g_norm[gw] = sqrtf(nrm);

    // Anchor row (anchors == arange in practice; reuse registers when so)
    int arow = anchors[gw];
    float4 a0, a1, a2, a3;
    if (arow == gw) {
        a0 = w0; a1 = w1; a2 = w2; a3 = w3;
    } else {
        size_t ra = (size_t)arow * D_VEC4;
        a0 = bb[ra + lane];
        a1 = bb[ra + lane + 32];
        a2 = bb[ra + lane + 64];
        a3 = bb[ra + lane + 96];
    }

    // Lane-distributed neighbor indices
    int pid = pos_idx[gw * P_DIM + (lane & (P_DIM - 1))];
    int nid = neg_idx[gw * Q_DIM + lane];

    float dpos = 0.0f;   // valid in lane k for k < P
    float dneg = 0.0f;   // valid in lane k

#pragma unroll
    for (int k = 0; k < P_DIM; k++) {
        int j = __shfl_sync(0xffffffffu, pid, k);
        size_t rb = (size_t)j * D_VEC4;
        float4 b0 = bb[rb + lane];
        float4 b1 = bb[rb + lane + 32];
        float4 b2 = bb[rb + lane + 64];
        float4 b3 = bb[rb + lane + 96];
        float ss = sqdiff4(a0, b0) + sqdiff4(a1, b1)
                 + sqdiff4(a2, b2) + sqdiff4(a3, b3);
        ss = warpSum(ss);
        if (lane == k) dpos = sqrtf(ss);
    }

#pragma unroll 4
    for (int k = 0; k < Q_DIM; k++) {
        int j = __shfl_sync(0xffffffffu, nid, k);
        size_t rb = (size_t)j * D_VEC4;
        float4 b0 = bb[rb + lane];
        float4 b1 = bb[rb + lane + 32];
        float4 b2 = bb[rb + lane + 64];
        float4 b3 = bb[rb + lane + 96];
        float ss = sqdiff4(a0, b0) + sqdiff4(a1, b1)
                 + sqdiff4(a2, b2) + sqdiff4(a3, b3);
        ss = warpSum(ss);
        if (lane == k) dneg = sqrtf(ss);
    }

    // logsumexp over pos distances (lanes 0..P-1 active)
    float vp = (lane < P_DIM) ? dpos : -1e30f;
    float mp = warpMax(vp);
    float ep = (lane < P_DIM) ? __expf(dpos - mp) : 0.0f;
    float sp = warpSum(ep);
    float pos_term = mp + __logf(sp);

    // logsumexp over MARGIN - neg distances (all 32 lanes)
    float vn = MARGIN - dneg;
    float mn = warpMax(vn);
    float sn = warpSum(__expf(vn - mn));
    float neg_term = mn + __logf(sn);

    if (lane == 0)
        g_per_anchor[gw] = fmaxf(0.0f, pos_term + neg_term);
}

// Deterministic final reduction: mean(per_anchor) + L2W * mean(norm)
__global__ void __launch_bounds__(1024)
reduce_kernel(float* __restrict__ out, int N) {
    __shared__ float sh[1024];
    float s = 0.0f;
    for (int i = threadIdx.x; i < N; i += 1024)
        s += g_per_anchor[i] + L2W * g_norm[i];
    sh[threadIdx.x] = s;
    __syncthreads();
#pragma unroll
    for (int o = 512; o > 0; o >>= 1) {
        if (threadIdx.x < o) sh[threadIdx.x] += sh[threadIdx.x + o];
        __syncthreads();
    }
    if (threadIdx.x == 0) out[0] = sh[0] / (float)N;
}

extern "C" void kernel_launch(void* const* d_in, const int* in_sizes, int n_in,
                              void* d_out, int out_size) {
    const float* batch   = (const float*)d_in[0];
    const int*   anchors = (const int*)d_in[1];
    const int*   pos_idx = (const int*)d_in[2];
    const int*   neg_idx = (const int*)d_in[3];
    int N = in_sizes[1];   // anchors has N elements

    int blocks = (N + 3) / 4;   // 4 warps per block, warp-per-anchor
    anchor_kernel<<<blocks, 128>>>(batch, anchors, pos_idx, neg_idx, N);
    reduce_kernel<<<1, 1024>>>((float*)d_out, N);
}